// round 14
// baseline (speedup 1.0000x reference)
#include <cuda_runtime.h>
#include <cuda_fp16.h>

#define BB 128
#define TT 256
#define KDIM 50
#define KK 2500            // K*K (gmem tile size, unpadded)
#define RSTRIDE 52         // padded smem row stride (floats): <=2-way LDS conflicts
#define SLOT (KDIM * RSTRIDE)   // 2600 floats per smem tile slot
#define START_TAG 48
#define END_TAG 49
#define NTH 128
#define SLACK 4.0f         // steady-state exp2 args center at -SLACK (fp16-safe)

__device__ float g_vec[2][BB][64];   // [dir][seq][tag]: absolute log2 alpha/beta at split
__device__ float g_gold[2][BB];      // gold partial per (dir, seq)
__device__ float g_apart[BB];        // combined per-seq log all-paths (nats)
__device__ float g_gpart[BB];        // combined per-seq gold
__device__ int   g_pair[BB];         // per-pair arrival counters (self-resetting)
__device__ int   g_count = 0;        // global arrival counter (self-resetting)

__device__ __forceinline__ void cp8(void* dst_smem, const void* src) {
    unsigned s = (unsigned)__cvta_generic_to_shared(dst_smem);
    asm volatile("cp.async.ca.shared.global [%0], [%1], 8;\n" :: "r"(s), "l"(src));
}
__device__ __forceinline__ void cp_commit() {
    asm volatile("cp.async.commit_group;\n");
}
template <int N>
__device__ __forceinline__ void cp_wait() {
    asm volatile("cp.async.wait_group %0;\n" :: "n"(N));
}
__device__ __forceinline__ float ex2f(float x) {
    float y; asm("ex2.approx.f32 %0, %1;" : "=f"(y) : "f"(x)); return y;
}
__device__ __forceinline__ float lg2f(float x) {
    float y; asm("lg2.approx.f32 %0, %1;" : "=f"(y) : "f"(x)); return y;
}
__device__ __forceinline__ __half2 pack_h2(float x1, float x2) {   // .x=x1, .y=x2
    unsigned p;
    asm("cvt.rn.f16x2.f32 %0, %1, %2;" : "=r"(p) : "f"(x2), "f"(x1));
    return *reinterpret_cast<__half2*>(&p);
}
__device__ __forceinline__ __half2 ex2_h2(__half2 ph) {
    unsigned p = *reinterpret_cast<unsigned*>(&ph);
    unsigned e;
    asm("ex2.approx.f16x2 %0, %1;" : "=r"(e) : "r"(p));
    return *reinterpret_cast<__half2*>(&e);
}

__global__ __launch_bounds__(NTH, 2)
void viterbi_pair_kernel(const float* __restrict__ scores,
                         const int* __restrict__ targets,
                         const int* __restrict__ lengths,
                         float* __restrict__ out) {
    __shared__ __align__(16) float raw[4 * SLOT + 320];  // padded tiles + ghost-overflow pad
    __shared__ __align__(16) float vbuf[2][64];          // double-buffered state vector
    __shared__ float r0s[2];                             // stale anchor, double buffered
    __shared__ float mxi[4];                             // init warp maxes
    __shared__ int   tgp[TT];                            // padded flat gold indices
    __shared__ int   sPair, sFin;
    __shared__ float sa[4], sg[4];

    const int bx   = blockIdx.x;
    const int dirB = bx >> 7;            // 0 = forward, 1 = backward
    const int b    = bx & (BB - 1);
    const int tid  = threadIdx.x;
    const int lane = tid & 31;
    const int wid  = tid >> 5;
    const int i    = tid >> 2;           // pair index 0..31 (active < 25)
    const int q    = tid & 3;            // j-quarter
    const int ic   = (i < 25) ? i : 24;  // clamped pair index (ghost threads)
    const int len  = lengths[b];
    const int m    = (len + 1) >> 1;
    const int nv   = dirB ? (len - m + 1) : m;   // visits incl. bwd virtual visit 0
    const float* base = scores + (size_t)b * TT * KK;
    const float L = 1.4426950408889634f; // log2(e)
    const __half2 clamp12 = __float2half2_rn(12.0f);

    {   // padded gold indices
        int t0 = targets[b * TT + tid];
        int t1 = targets[b * TT + tid + NTH];
        tgp[tid]       = (t0 / KDIM) * RSTRIDE + (t0 % KDIM);
        tgp[tid + NTH] = (t1 / KDIM) * RSTRIDE + (t1 % KDIM);
    }
    // zero in-row pads (floats 50,51 of each row, all 4 slots) — never cp.async'd
    for (int idx = tid; idx < 200; idx += NTH) {
        int s = idx / 50, rr = idx - (idx / 50) * 50;
        raw[s * SLOT + rr * RSTRIDE + 50] = 0.f;
        raw[s * SLOT + rr * RSTRIDE + 51] = 0.f;
    }
    // zero trailing ghost pad
    for (int idx = tid; idx < 320; idx += NTH) raw[4 * SLOT + idx] = 0.f;

    auto issue = [&](int vv) {
        bool real = (vv < nv) && (!dirB || vv >= 1);
        if (real) {
            int t = dirB ? (len - vv) : vv;
            const float* src = base + (size_t)t * KK;
            float* dst = raw + (vv & 3) * SLOT;
            // 1250 8-byte chunks: src rr*200+8c and dst rr*208+8c both 8B-aligned
            #pragma unroll
            for (int u2 = 0; u2 < 10; ++u2) {
                int c8 = tid + u2 * NTH;
                if (c8 < 1250) {
                    int rr = c8 / 25, cc = c8 - rr * 25;
                    cp8(dst + rr * RSTRIDE + cc * 2, src + rr * KDIM + cc * 2);
                }
            }
        }
        cp_commit();                     // always commit: static group accounting
    };

    issue(0); issue(1); issue(2); issue(3);
    cp_wait<3>();
    __syncthreads();                     // tile 0 + pad zeros certified

    float gold = 0.f, shift = 0.f, dcur = 0.f;
    float r0, r1;

    // ---- init state at the starting end ----
    if (!dirB) {
        r0 = raw[START_TAG * RSTRIDE + 2 * ic] * L;
        r1 = raw[START_TAG * RSTRIDE + 2 * ic + 1] * L;
        float mw = fmaxf(r0, r1);
        #pragma unroll
        for (int o = 16; o > 0; o >>= 1)
            mw = fmaxf(mw, __shfl_xor_sync(0xFFFFFFFFu, mw, o));
        if (lane == 0) mxi[wid] = mw;
        if (tid == 0) gold += raw[tgp[0]];
    } else {
        r0 = -1e30f;
        r1 = (ic == 24) ? 0.f : -1e30f;  // col/row 49 == END_TAG
    }
    __syncthreads();                     // mxi visible
    dcur = dirB ? 0.f : (fmaxf(fmaxf(mxi[0], mxi[1]), fmaxf(mxi[2], mxi[3])) + SLACK);
    if (q == 0 && i < 25) {
        vbuf[1][2 * i]     = r0 - dcur;
        vbuf[1][2 * i + 1] = r1 - dcur;
    }
    if (tid < 64) {
        vbuf[0][tid] = -1e30f;           // buffer 0 fully poisoned (pads persist)
        if (tid >= 50) vbuf[1][tid] = -1e30f;
    }
    if (tid == 0) r0s[0] = dirB ? 0.f : r0;   // anchor (tid0 holds col 0 fwd)

    for (int v = 1; v < nv; ++v) {
        cp_wait<2>();                    // tile v landed
        __syncthreads();                 // SINGLE barrier: tile v + vbuf[v&1] certified

        const float* sb = raw + (v & 3) * SLOT;
        if (tid == 0) gold += sb[tgp[dirB ? (len - v) : v]];

        const float* vb = vbuf[v & 1];
        __half2 acc0 = __float2half2_rn(0.f);
        __half2 acc1 = __float2half2_rn(0.f);
        if (!dirB) {                     // fwd: thread owns cols (2ic, 2ic+1)
            const float* colp = sb + 2 * ic;
            #pragma unroll
            for (int u = 0; u < 7; ++u) {
                int p = q + 4 * u;       // j-pair index 0..27 (ghost >=25 killed by vbuf pad)
                float2 av = *(const float2*)(vb + 2 * p);
                float2 s0 = *(const float2*)(colp + (2 * p) * RSTRIDE);
                float2 s1 = *(const float2*)(colp + (2 * p + 1) * RSTRIDE);
                __half2 e0 = ex2_h2(__hmin2(pack_h2(__fmaf_rn(s0.x, L, av.x),
                                                    __fmaf_rn(s0.y, L, av.x)), clamp12));
                __half2 e1 = ex2_h2(__hmin2(pack_h2(__fmaf_rn(s1.x, L, av.y),
                                                    __fmaf_rn(s1.y, L, av.y)), clamp12));
                acc0 = __hadd2(acc0, e0);
                acc1 = __hadd2(acc1, e1);
            }
        } else {                         // bwd: thread owns rows (2ic, 2ic+1)
            const float* row0 = sb + (2 * ic) * RSTRIDE;
            const float* row1 = sb + (2 * ic + 1) * RSTRIDE;
            #pragma unroll
            for (int u = 0; u < 7; ++u) {
                int p = q + 4 * u;
                float2 bv = *(const float2*)(vb + 2 * p);
                float2 s0 = *(const float2*)(row0 + 2 * p);
                float2 s1 = *(const float2*)(row1 + 2 * p);
                __half2 e0 = ex2_h2(__hmin2(pack_h2(__fmaf_rn(s0.x, L, bv.x),
                                                    __fmaf_rn(s1.x, L, bv.x)), clamp12));
                __half2 e1 = ex2_h2(__hmin2(pack_h2(__fmaf_rn(s0.y, L, bv.y),
                                                    __fmaf_rn(s1.y, L, bv.y)), clamp12));
                acc0 = __hadd2(acc0, e0);
                acc1 = __hadd2(acc1, e1);
            }
        }
        issue(v + 3);                    // into slot (v-1)&3 (certified drained by barrier)

        float2 tf0 = __half22float2(acc0);   // combine in fp32 (overflow-safe)
        float2 tf1 = __half22float2(acc1);
        float t0 = tf0.x + tf1.x;
        float t1 = tf0.y + tf1.y;
        t0 += __shfl_xor_sync(0xFFFFFFFFu, t0, 1);   // q-group reduce (4 lanes)
        t1 += __shfl_xor_sync(0xFFFFFFFFu, t1, 1);
        t0 += __shfl_xor_sync(0xFFFFFFFFu, t0, 2);
        t1 += __shfl_xor_sync(0xFFFFFFFFu, t1, 2);
        r0 = lg2f(fmaxf(t0, 1e-35f));                // never -inf
        r1 = lg2f(fmaxf(t1, 1e-35f));
        shift += dcur;
        float dn = r0s[(v - 1) & 1] + SLACK;         // stale anchor
        if (q == 0 && i < 25)
            *(float2*)&vbuf[(v + 1) & 1][2 * i] = make_float2(r0 - dn, r1 - dn);
        dcur = dn;
        if (tid == 0) r0s[v & 1] = r0;
    }

    cp_wait<0>();
    __syncthreads();

    // ---- publish half-result ----
    if (q == 0 && i < 25) {
        g_vec[dirB][b][2 * i]     = r0 + shift;   // absolute log2
        g_vec[dirB][b][2 * i + 1] = r1 + shift;
    }
    if (tid == 0) g_gold[dirB][b] = gold;
    __syncthreads();
    if (tid == 0) {
        __threadfence();
        sPair = atomicAdd(&g_pair[b], 1);
    }
    __syncthreads();

    if (sPair == 1) {                    // second arrival: combine the pair
        __threadfence();
        if (tid < 32) {
            int j2 = tid + 32;
            float x1 = g_vec[0][b][tid] + g_vec[1][b][tid];
            float x2 = (j2 < KDIM) ? (g_vec[0][b][j2] + g_vec[1][b][j2]) : -1e30f;
            float mx = fmaxf(x1, x2);
            #pragma unroll
            for (int o = 16; o > 0; o >>= 1)
                mx = fmaxf(mx, __shfl_xor_sync(0xFFFFFFFFu, mx, o));
            float s = ex2f(x1 - mx) + ex2f(x2 - mx);
            #pragma unroll
            for (int o = 16; o > 0; o >>= 1)
                s += __shfl_xor_sync(0xFFFFFFFFu, s, o);
            if (tid == 0) {
                g_apart[b] = (mx + lg2f(s)) * 0.6931471805599453f;
                g_gpart[b] = g_gold[0][b] + g_gold[1][b];
                g_pair[b]  = 0;          // reset for next graph replay
            }
        }
    }
    __syncthreads();
    if (tid == 0) {
        __threadfence();
        int old = atomicAdd(&g_count, 1);
        sFin = (old == 2 * BB - 1) ? 1 : 0;
    }
    __syncthreads();

    if (sFin) {                          // very last CTA: deterministic final reduce
        __threadfence();
        float a  = g_apart[tid];         // NTH == BB == 128
        float gd = g_gpart[tid];
        #pragma unroll
        for (int o = 16; o > 0; o >>= 1) {
            a  += __shfl_down_sync(0xFFFFFFFFu, a, o);
            gd += __shfl_down_sync(0xFFFFFFFFu, gd, o);
        }
        if (lane == 0) { sa[wid] = a; sg[wid] = gd; }
        __syncthreads();
        if (tid == 0) {
            float A = sa[0] + sa[1] + sa[2] + sa[3];
            float G = sg[0] + sg[1] + sg[2] + sg[3];
            out[0] = (A - G) / (float)BB;
            atomicExch(&g_count, 0);     // reset for next graph replay
        }
    }
}

extern "C" void kernel_launch(void* const* d_in, const int* in_sizes, int n_in,
                              void* d_out, int out_size) {
    const float* scores  = (const float*)d_in[0];
    const int*   targets = (const int*)d_in[1];
    const int*   lengths = (const int*)d_in[2];
    // d_in[3] = tmap_correct (unused scalar)
    viterbi_pair_kernel<<<2 * BB, NTH>>>(scores, targets, lengths, (float*)d_out);
}

// round 15
// speedup vs baseline: 1.0214x; 1.0214x over previous
#include <cuda_runtime.h>
#include <cuda_fp16.h>

#define BB 128
#define TT 256
#define KDIM 50
#define KK 2500          // K*K
#define NSLOT 8          // prefetch ring depth (80 KB)
#define START_TAG 48
#define END_TAG 49
#define NTH 64
#define SLACK 4.0f       // steady-state exp2 args center at -SLACK (fp16-safe)

__device__ float g_vec[2][BB][64];   // [dir][seq][tag]: absolute log2 alpha/beta at split
__device__ float g_gold[2][BB];      // gold partial per (dir, seq)
__device__ float g_apart[BB];        // combined per-seq log all-paths (nats)
__device__ float g_gpart[BB];        // combined per-seq gold
__device__ int   g_pair[BB];         // per-pair arrival counters (self-resetting)
__device__ int   g_count = 0;        // global arrival counter (self-resetting)

__device__ __forceinline__ void cp16(void* dst_smem, const void* src) {
    unsigned s = (unsigned)__cvta_generic_to_shared(dst_smem);
    asm volatile("cp.async.cg.shared.global [%0], [%1], 16;\n" :: "r"(s), "l"(src));
}
__device__ __forceinline__ void cp_commit() {
    asm volatile("cp.async.commit_group;\n");
}
template <int N>
__device__ __forceinline__ void cp_wait() {
    asm volatile("cp.async.wait_group %0;\n" :: "n"(N));
}
__device__ __forceinline__ float ex2f(float x) {
    float y; asm("ex2.approx.f32 %0, %1;" : "=f"(y) : "f"(x)); return y;
}
__device__ __forceinline__ float lg2f(float x) {
    float y; asm("lg2.approx.f32 %0, %1;" : "=f"(y) : "f"(x)); return y;
}
__device__ __forceinline__ __half2 pack_h2(float x1, float x2) {
    unsigned p;
    asm("cvt.rn.f16x2.f32 %0, %1, %2;" : "=r"(p) : "f"(x2), "f"(x1));
    return *reinterpret_cast<__half2*>(&p);
}
__device__ __forceinline__ __half2 ex2_h2(__half2 ph) {
    unsigned p = *reinterpret_cast<unsigned*>(&ph);
    unsigned e;
    asm("ex2.approx.f16x2 %0, %1;" : "=r"(e) : "r"(p));
    return *reinterpret_cast<__half2*>(&e);
}

__global__ __launch_bounds__(NTH, 2)
void viterbi_deep_kernel(const float* __restrict__ scores,
                         const int* __restrict__ targets,
                         const int* __restrict__ lengths,
                         float* __restrict__ out) {
    extern __shared__ __align__(16) float raw[];   // NSLOT * KK floats (80 KB ring)
    __shared__ __align__(8) float vbuf[2][64];     // double-buffered state vector
    __shared__ float r0s[2];                       // stale anchor, double buffered
    __shared__ float mxi[2];                       // init warp maxes
    __shared__ int   tg[TT];
    __shared__ int   sPair, sFin;
    __shared__ float sa[2], sg[2];

    const int bx   = blockIdx.x;
    const int dirB = bx >> 7;            // 0 = forward, 1 = backward
    const int b    = bx & (BB - 1);
    const int tid  = threadIdx.x;
    const int lane = tid & 31;
    const int wid  = tid >> 5;
    const int c    = tid;                // output tag column (active < 50)
    const int len  = lengths[b];
    const int m    = (len + 1) >> 1;
    const int nv   = dirB ? (len - m + 1) : m;   // visits incl. bwd virtual visit 0
    const float* base = scores + (size_t)b * TT * KK;
    const float L = 1.4426950408889634f; // log2(e)
    const __half2 clamp12 = __float2half2_rn(12.0f);
    const bool act = (c < KDIM);

    #pragma unroll
    for (int i = 0; i < 4; ++i) tg[tid + i * NTH] = targets[b * TT + tid + i * NTH];

    auto issue = [&](int vv) {
        bool real = (vv < nv) && (!dirB || vv >= 1);
        if (real) {
            int t = dirB ? (len - vv) : vv;
            const float4* src = (const float4*)(base + (size_t)t * KK);
            float4* dst = (float4*)(raw + (vv & (NSLOT - 1)) * KK);
            #pragma unroll
            for (int i = 0; i < 10; ++i) {
                int c4 = tid + i * NTH;
                if (c4 < 625) cp16(dst + c4, src + c4);
            }
        }
        cp_commit();                     // always commit: static group accounting
    };

    // prologue: fill 7 slots ahead
    #pragma unroll
    for (int vv = 0; vv < 7; ++vv) issue(vv);
    cp_wait<6>();                        // tile 0 landed
    __syncthreads();                     // visit 0 certified

    float gold = 0.f, r = 0.f, shift = 0.f, dcur = 0.f;

    // ---- init state at the starting end ----
    if (!dirB) {
        r = act ? raw[START_TAG * KDIM + c] * L : -1e30f;
        float mw = r;
        #pragma unroll
        for (int o = 16; o > 0; o >>= 1)
            mw = fmaxf(mw, __shfl_xor_sync(0xFFFFFFFFu, mw, o));
        if (lane == 0) mxi[wid] = mw;
        if (tid == 0) gold += raw[tg[0]];
    } else {
        r = (c == END_TAG) ? 0.f : -1e30f;
    }
    __syncthreads();                     // mxi visible
    if (!dirB) {
        dcur = fmaxf(mxi[0], mxi[1]) + SLACK;   // exact-max anchor at init
        vbuf[1][c] = act ? (r - dcur) : -1e30f;
        vbuf[0][c] = -1e30f;
        if (c == 0) r0s[0] = r;
    } else {
        dcur = 0.f;
        vbuf[1][c] = r;
        vbuf[0][c] = -1e30f;
        if (c == 0) r0s[0] = 0.f;
    }

    for (int v = 1; v < nv; ++v) {
        cp_wait<5>();                    // tile v landed (issued 6 steps ago)
        __syncthreads();                 // SINGLE barrier: tile v + vbuf[v&1] certified
        issue(v + 6);                    // into slot (v-2)&7 (drained 2 steps ago)

        const float* sb = raw + (v & (NSLOT - 1)) * KK;
        const int t = dirB ? (len - v) : v;
        if (tid == 0) gold += sb[tg[t]];

        if (act) {
            const float* ab = vbuf[v & 1];
            __half2 acc0 = __float2half2_rn(0.f);
            __half2 acc1 = __float2half2_rn(0.f);
            if (!dirB) {                 // fwd: addr j*50 + c (column access)
                #pragma unroll
                for (int p = 0; p < 25; ++p) {
                    int j = 2 * p;
                    float x1 = __fmaf_rn(sb[j * KDIM + c],       L, ab[j]);
                    float x2 = __fmaf_rn(sb[(j + 1) * KDIM + c], L, ab[j + 1]);
                    __half2 e = ex2_h2(__hmin2(pack_h2(x1, x2), clamp12));
                    if (p & 1) acc1 = __hadd2(acc1, e);
                    else       acc0 = __hadd2(acc0, e);
                }
            } else {                     // bwd: addr c*50 + k (row access, float2)
                const float2* row = (const float2*)(sb + c * KDIM);
                #pragma unroll
                for (int p = 0; p < 25; ++p) {
                    float2 sv = row[p];
                    int j = 2 * p;
                    float x1 = __fmaf_rn(sv.x, L, ab[j]);
                    float x2 = __fmaf_rn(sv.y, L, ab[j + 1]);
                    __half2 e = ex2_h2(__hmin2(pack_h2(x1, x2), clamp12));
                    if (p & 1) acc1 = __hadd2(acc1, e);
                    else       acc0 = __hadd2(acc0, e);
                }
            }
            float2 f0 = __half22float2(acc0);
            float2 f1 = __half22float2(acc1);
            float tot = (f0.x + f1.x) + (f0.y + f1.y);
            r = lg2f(fmaxf(tot, 1e-35f));           // never -inf
            shift += dcur;
            float dn = r0s[(v - 1) & 1] + SLACK;    // stale anchor r_{v-1}[0]
            vbuf[(v + 1) & 1][c] = r - dn;          // write OTHER buffer (race-free)
            dcur = dn;
            if (c == 0) r0s[v & 1] = r;
        } else {
            vbuf[(v + 1) & 1][c] = -1e30f;          // keep pads poisoned
        }
    }

    cp_wait<0>();
    __syncthreads();

    // ---- publish half-result ----
    if (act) g_vec[dirB][b][c] = r + shift;   // absolute log2
    if (tid == 0) g_gold[dirB][b] = gold;
    __syncthreads();
    if (tid == 0) {
        __threadfence();
        sPair = atomicAdd(&g_pair[b], 1);
    }
    __syncthreads();

    if (sPair == 1) {                    // second arrival: combine the pair
        __threadfence();
        if (tid < 32) {
            int j2 = tid + 32;
            float x1 = g_vec[0][b][tid] + g_vec[1][b][tid];
            float x2 = (j2 < KDIM) ? (g_vec[0][b][j2] + g_vec[1][b][j2]) : -1e30f;
            float mx = fmaxf(x1, x2);
            #pragma unroll
            for (int o = 16; o > 0; o >>= 1)
                mx = fmaxf(mx, __shfl_xor_sync(0xFFFFFFFFu, mx, o));
            float s = ex2f(x1 - mx) + ex2f(x2 - mx);
            #pragma unroll
            for (int o = 16; o > 0; o >>= 1)
                s += __shfl_xor_sync(0xFFFFFFFFu, s, o);
            if (tid == 0) {
                g_apart[b] = (mx + lg2f(s)) * 0.6931471805599453f;
                g_gpart[b] = g_gold[0][b] + g_gold[1][b];
                g_pair[b]  = 0;          // reset for next graph replay
            }
        }
    }
    __syncthreads();
    if (tid == 0) {
        __threadfence();
        int old = atomicAdd(&g_count, 1);
        sFin = (old == 2 * BB - 1) ? 1 : 0;
    }
    __syncthreads();

    if (sFin) {                          // very last CTA: deterministic final reduce
        __threadfence();
        float a  = g_apart[tid] + g_apart[tid + 64];
        float gd = g_gpart[tid] + g_gpart[tid + 64];
        #pragma unroll
        for (int o = 16; o > 0; o >>= 1) {
            a  += __shfl_down_sync(0xFFFFFFFFu, a, o);
            gd += __shfl_down_sync(0xFFFFFFFFu, gd, o);
        }
        if (lane == 0) { sa[wid] = a; sg[wid] = gd; }
        __syncthreads();
        if (tid == 0) {
            out[0] = ((sa[0] + sa[1]) - (sg[0] + sg[1])) / (float)BB;
            atomicExch(&g_count, 0);     // reset for next graph replay
        }
    }
}

extern "C" void kernel_launch(void* const* d_in, const int* in_sizes, int n_in,
                              void* d_out, int out_size) {
    const float* scores  = (const float*)d_in[0];
    const int*   targets = (const int*)d_in[1];
    const int*   lengths = (const int*)d_in[2];
    // d_in[3] = tmap_correct (unused scalar)
    const int smem = NSLOT * KK * sizeof(float);   // 80 KB ring
    cudaFuncSetAttribute(viterbi_deep_kernel,
                         cudaFuncAttributeMaxDynamicSharedMemorySize, smem);
    viterbi_deep_kernel<<<2 * BB, NTH, smem>>>(scores, targets, lengths,
                                               (float*)d_out);
}

// round 16
// speedup vs baseline: 1.0274x; 1.0059x over previous
#include <cuda_runtime.h>
#include <cuda_fp16.h>

#define BB 128
#define TT 256
#define KDIM 50
#define KK 2500          // K*K
#define START_TAG 48
#define END_TAG 49
#define NTH 128
#define SLACK 4.0f       // steady-state exp2 args center at -SLACK (fp16-safe)

__device__ float g_apart[BB];        // per-seq log all-paths (nats)
__device__ float g_gpart[BB];        // per-seq gold
__device__ int   g_count = 0;        // arrival counter (self-resetting)

__device__ __forceinline__ void cp16(void* dst_smem, const void* src) {
    unsigned s = (unsigned)__cvta_generic_to_shared(dst_smem);
    asm volatile("cp.async.cg.shared.global [%0], [%1], 16;\n" :: "r"(s), "l"(src));
}
__device__ __forceinline__ void cp_commit() {
    asm volatile("cp.async.commit_group;\n");
}
template <int N>
__device__ __forceinline__ void cp_wait() {
    asm volatile("cp.async.wait_group %0;\n" :: "n"(N));
}
__device__ __forceinline__ void dir_bar(int dir) {   // 2-warp named barrier per direction
    asm volatile("bar.sync %0, 64;" :: "r"(dir + 1) : "memory");
}
__device__ __forceinline__ float ex2f(float x) {
    float y; asm("ex2.approx.f32 %0, %1;" : "=f"(y) : "f"(x)); return y;
}
__device__ __forceinline__ float lg2f(float x) {
    float y; asm("lg2.approx.f32 %0, %1;" : "=f"(y) : "f"(x)); return y;
}
__device__ __forceinline__ __half2 pack_h2(float x1, float x2) {
    unsigned p;
    asm("cvt.rn.f16x2.f32 %0, %1, %2;" : "=r"(p) : "f"(x2), "f"(x1));
    return *reinterpret_cast<__half2*>(&p);
}
__device__ __forceinline__ __half2 ex2_h2(__half2 ph) {
    unsigned p = *reinterpret_cast<unsigned*>(&ph);
    unsigned e;
    asm("ex2.approx.f16x2 %0, %1;" : "=r"(e) : "r"(p));
    return *reinterpret_cast<__half2*>(&e);
}

__global__ __launch_bounds__(NTH, 1)
void viterbi_fused_kernel(const float* __restrict__ scores,
                          const int* __restrict__ targets,
                          const int* __restrict__ lengths,
                          float* __restrict__ out) {
    extern __shared__ __align__(16) float raw[];   // 2 dirs x 4 slots x KK (80 KB)
    __shared__ __align__(8) float vbuf[2][2][64];  // [dir][parity][tag]
    __shared__ float r0s[2][2];                    // stale anchor per dir, dbl-buffered
    __shared__ float mxi[2];                       // fwd init warp maxes
    __shared__ float avecs[2][64];                 // absolute log2 alpha/beta at split
    __shared__ float goldS[2];
    __shared__ int   tg[TT];
    __shared__ int   sFin;
    __shared__ float sa[4], sg[4];

    const int b    = blockIdx.x;
    const int tid  = threadIdx.x;
    const int lane = tid & 31;
    const int wid  = tid >> 5;
    const int dir  = tid >> 6;           // 0 = forward (warps 0,1), 1 = backward (2,3)
    const int c    = tid & 63;           // tag column (active < 50)
    const int len  = lengths[b];
    const int m    = (len + 1) >> 1;
    const int nv   = dir ? (len - m + 1) : m;    // visits incl. bwd virtual visit 0
    const float* base = scores + (size_t)b * TT * KK;
    float* dslot = raw + dir * 4 * KK;           // this direction's 4-slot ring
    const float L = 1.4426950408889634f; // log2(e)
    const __half2 clamp12 = __float2half2_rn(12.0f);
    const bool act = (c < KDIM);

    tg[tid] = targets[b * TT + tid];
    tg[tid + NTH] = targets[b * TT + tid + NTH];

    auto issue = [&](int vv) {
        bool real = (vv < nv) && (!dir || vv >= 1);
        if (real) {
            int t = dir ? (len - vv) : vv;
            const float4* src = (const float4*)(base + (size_t)t * KK);
            float4* dst = (float4*)(dslot + (vv & 3) * KK);
            #pragma unroll
            for (int i = 0; i < 10; ++i) {
                int c4 = c + i * 64;
                if (c4 < 625) cp16(dst + c4, src + c4);
            }
        }
        cp_commit();                     // always commit: static group accounting
    };

    issue(0); issue(1); issue(2); issue(3);
    cp_wait<3>();
    __syncthreads();                     // tiles 0 + tg certified for both dirs

    float gold = 0.f, r = 0.f, shift = 0.f, dcur = 0.f;

    // ---- init state at this direction's starting end ----
    if (!dir) {
        r = act ? dslot[START_TAG * KDIM + c] * L : -1e30f;
        float mw = r;
        #pragma unroll
        for (int o = 16; o > 0; o >>= 1)
            mw = fmaxf(mw, __shfl_xor_sync(0xFFFFFFFFu, mw, o));
        if (lane == 0) mxi[wid] = mw;    // wid = 0 or 1
        if (tid == 0) gold += dslot[tg[0]];
    } else {
        r = (c == END_TAG) ? 0.f : -1e30f;
    }
    dir_bar(dir);                        // mxi visible within fwd group
    if (!dir) {
        dcur = fmaxf(mxi[0], mxi[1]) + SLACK;   // exact-max anchor at init
        vbuf[0][1][c] = act ? (r - dcur) : -1e30f;
        vbuf[0][0][c] = -1e30f;
        if (c == 0) r0s[0][0] = r;
    } else {
        dcur = 0.f;
        vbuf[1][1][c] = r;
        vbuf[1][0][c] = -1e30f;
        if (c == 0) r0s[1][0] = 0.f;
    }

    for (int v = 1; v < nv; ++v) {
        cp_wait<2>();                    // tile v landed (this thread's chunks)
        dir_bar(dir);                    // tile v + vbuf[dir][v&1] certified (own group)
        issue(v + 3);                    // into slot (v-1)&3 (fully drained)

        const float* sb = dslot + (v & 3) * KK;
        if (c == 0) gold += sb[tg[dir ? (len - v) : v]];

        if (act) {
            const float* ab = vbuf[dir][v & 1];
            __half2 acc0 = __float2half2_rn(0.f);
            __half2 acc1 = __float2half2_rn(0.f);
            if (!dir) {                  // fwd: addr j*50 + c (column access)
                #pragma unroll
                for (int p = 0; p < 25; ++p) {
                    int j = 2 * p;
                    float x1 = __fmaf_rn(sb[j * KDIM + c],       L, ab[j]);
                    float x2 = __fmaf_rn(sb[(j + 1) * KDIM + c], L, ab[j + 1]);
                    __half2 e = ex2_h2(__hmin2(pack_h2(x1, x2), clamp12));
                    if (p & 1) acc1 = __hadd2(acc1, e);
                    else       acc0 = __hadd2(acc0, e);
                }
            } else {                     // bwd: addr c*50 + k (row access, float2)
                const float2* row = (const float2*)(sb + c * KDIM);
                #pragma unroll
                for (int p = 0; p < 25; ++p) {
                    float2 sv = row[p];
                    int j = 2 * p;
                    float x1 = __fmaf_rn(sv.x, L, ab[j]);
                    float x2 = __fmaf_rn(sv.y, L, ab[j + 1]);
                    __half2 e = ex2_h2(__hmin2(pack_h2(x1, x2), clamp12));
                    if (p & 1) acc1 = __hadd2(acc1, e);
                    else       acc0 = __hadd2(acc0, e);
                }
            }
            float2 f0 = __half22float2(acc0);
            float2 f1 = __half22float2(acc1);
            float tot = (f0.x + f1.x) + (f0.y + f1.y);
            r = lg2f(fmaxf(tot, 1e-35f));           // never -inf
            shift += dcur;
            float dn = r0s[dir][(v - 1) & 1] + SLACK;   // stale anchor r_{v-1}[0]
            vbuf[dir][(v + 1) & 1][c] = r - dn;     // write other parity (pads persist)
            dcur = dn;
            if (c == 0) r0s[dir][v & 1] = r;
        }
    }

    cp_wait<0>();
    dir_bar(dir);

    // ---- publish per-direction result into shared, then combine in-CTA ----
    avecs[dir][c] = act ? (r + shift) : -1e30f;     // absolute log2
    if (c == 0) goldS[dir] = gold;
    __syncthreads();                     // both directions complete

    if (tid < 32) {
        int j2 = tid + 32;
        float x1 = avecs[0][tid] + avecs[1][tid];
        float x2 = (j2 < KDIM) ? (avecs[0][j2] + avecs[1][j2]) : -1e30f;
        float mx = fmaxf(x1, x2);
        #pragma unroll
        for (int o = 16; o > 0; o >>= 1)
            mx = fmaxf(mx, __shfl_xor_sync(0xFFFFFFFFu, mx, o));
        float s = ex2f(x1 - mx) + ex2f(x2 - mx);
        #pragma unroll
        for (int o = 16; o > 0; o >>= 1)
            s += __shfl_xor_sync(0xFFFFFFFFu, s, o);
        if (tid == 0) {
            g_apart[b] = (mx + lg2f(s)) * 0.6931471805599453f;
            g_gpart[b] = goldS[0] + goldS[1];
        }
    }
    __syncthreads();
    if (tid == 0) {
        __threadfence();
        int old = atomicAdd(&g_count, 1);
        sFin = (old == BB - 1) ? 1 : 0;
    }
    __syncthreads();

    if (sFin) {                          // very last CTA: deterministic final reduce
        __threadfence();
        float a  = g_apart[tid];         // NTH == BB == 128
        float gd = g_gpart[tid];
        #pragma unroll
        for (int o = 16; o > 0; o >>= 1) {
            a  += __shfl_down_sync(0xFFFFFFFFu, a, o);
            gd += __shfl_down_sync(0xFFFFFFFFu, gd, o);
        }
        if (lane == 0) { sa[wid] = a; sg[wid] = gd; }
        __syncthreads();
        if (tid == 0) {
            float A = sa[0] + sa[1] + sa[2] + sa[3];
            float G = sg[0] + sg[1] + sg[2] + sg[3];
            out[0] = (A - G) / (float)BB;
            atomicExch(&g_count, 0);     // reset for next graph replay
        }
    }
}

extern "C" void kernel_launch(void* const* d_in, const int* in_sizes, int n_in,
                              void* d_out, int out_size) {
    const float* scores  = (const float*)d_in[0];
    const int*   targets = (const int*)d_in[1];
    const int*   lengths = (const int*)d_in[2];
    // d_in[3] = tmap_correct (unused scalar)
    const int smem = 2 * 4 * KK * sizeof(float);   // 80 KB (two 4-slot rings)
    cudaFuncSetAttribute(viterbi_fused_kernel,
                         cudaFuncAttributeMaxDynamicSharedMemorySize, smem);
    viterbi_fused_kernel<<<BB, NTH, smem>>>(scores, targets, lengths,
                                            (float*)d_out);
}